// round 12
// baseline (speedup 1.0000x reference)
#include <cuda_runtime.h>
#include <cuda_bf16.h>

typedef unsigned int u32;
typedef unsigned short us16;

#define NB 8
#define NC 512
#define NQ 64
#define NHW 4096
#define BCHW (NB*NC*NHW)
#define CHW  (NC*NHW)

// ------------------------- device scratch -------------------------
__device__ __align__(16) us16  g_x2b [BCHW];
__device__ __align__(16) us16  g_x1b [BCHW];
__device__ __align__(16) us16  g_xT2 [BCHW];
__device__ __align__(16) us16  g_xT1 [BCHW];
__device__ __align__(16) us16  g_qkb [NB*NHW*128];   // [b][pix][q0..63,k0..63] bf16
__device__ __align__(16) float g_att [NB*NHW*128];   // only [0:64] (E_H) used
__device__ __align__(16) us16  g_attb[NB*NHW*128];
__device__ __align__(16) us16  g_aggP[2*BCHW];       // dir0 partial, channel-last
__device__ __align__(16) us16  g_wqk[128*NC];
__device__ __align__(16) us16  g_wv [NC*NC];

// ------------------------- helpers -------------------------
__device__ __forceinline__ us16 f2b(float f){
    __nv_bfloat16 h = __float2bfloat16(f);
    return *reinterpret_cast<us16*>(&h);
}
__device__ __forceinline__ float b2f(us16 u){
    __nv_bfloat16 h; *reinterpret_cast<us16*>(&h) = u;
    return __bfloat162float(h);
}
__device__ __forceinline__ u32 pk2(float a, float b){
    return (u32)f2b(a) | ((u32)f2b(b) << 16);
}
__device__ __forceinline__ u32 addbf2(u32 s, u32 p){
    float lo = b2f((us16)(s & 0xffff)) + b2f((us16)(p & 0xffff));
    float hi = b2f((us16)(s >> 16))    + b2f((us16)(p >> 16));
    return pk2(lo, hi);
}
__device__ __forceinline__ void mma_bf16(float* d, const u32* a, const u32* b){
    asm volatile(
        "mma.sync.aligned.m16n8k16.row.col.f32.bf16.bf16.f32 "
        "{%0,%1,%2,%3}, {%4,%5,%6,%7}, {%8,%9}, {%0,%1,%2,%3};\n"
        : "+f"(d[0]), "+f"(d[1]), "+f"(d[2]), "+f"(d[3])
        : "r"(a[0]), "r"(a[1]), "r"(a[2]), "r"(a[3]), "r"(b[0]), "r"(b[1]));
}
__device__ __forceinline__ void cpa16(void* s, const void* g){
    u32 sa = (u32)__cvta_generic_to_shared(s);
    asm volatile("cp.async.cg.shared.global [%0], [%1], 16;\n" :: "r"(sa), "l"(g));
}

// -------- prep: x -> bf16 (normal + transposed plane); y==2 converts weights --------
__global__ __launch_bounds__(256) void k_prep(const float* __restrict__ x2,
                                              const float* __restrict__ x1,
                                              const float* __restrict__ qw,
                                              const float* __restrict__ kw,
                                              const float* __restrict__ vw){
    int t = threadIdx.x;
    if (blockIdx.y == 2){
        if (blockIdx.x >= 1280) return;
        int i = blockIdx.x * 256 + t;
        if (i < 128 * NC){
            int o = i >> 9, c = i & 511;
            g_wqk[i] = f2b(o < 64 ? qw[o*NC + c] : kw[(o-64)*NC + c]);
        } else {
            int j = i - 128*NC;
            g_wv[j] = f2b(vw[j]);
        }
        return;
    }
    int plane = blockIdx.x, which = blockIdx.y;
    const float* x = (which ? x1    : x2   ) + (size_t)plane * 4096;
    us16*       on = (which ? g_x1b : g_x2b) + (size_t)plane * 4096;
    us16*       ot = (which ? g_xT1 : g_xT2) + (size_t)plane * 4096;
    __shared__ float sm[64][65];
    const float4* x4 = (const float4*)x;
#pragma unroll
    for (int j = 0; j < 4; j++){
        int idx4 = j*256 + t;
        float4 v = x4[idx4];
        int h = idx4 >> 4, w4 = (idx4 & 15) * 4;
        sm[h][w4  ] = v.x; sm[h][w4+1] = v.y;
        sm[h][w4+2] = v.z; sm[h][w4+3] = v.w;
        ((uint2*)on)[idx4] = make_uint2(pk2(v.x, v.y), pk2(v.z, v.w));
    }
    __syncthreads();
#pragma unroll
    for (int j = 0; j < 4; j++){
        int idx4 = j*256 + t;
        int w = idx4 >> 4, h4 = (idx4 & 15) * 4;
        ((uint2*)ot)[idx4] = make_uint2(pk2(sm[h4][w],   sm[h4+1][w]),
                                        pk2(sm[h4+2][w], sm[h4+3][w]));
    }
}

// -------- gemm0: [q_w;k_w](128x512) * x2b -> q,k channel-last bf16 (+bias) --------
#define AS0(st,i,j) dsm[(st)*9216 + (i)*72 + (j)]
#define BS0(st,i,j) dsm[18432 + (st)*8704 + (i)*136 + (j)]
#define STG0(p,c)   dsm[(p)*136 + (c)]
#define GEMM0_SMEM ((18432 + 2*8704) * 2)
__global__ __launch_bounds__(256) void k_gemm0(
    const float* __restrict__ bias0, const float* __restrict__ bias1)
{
    extern __shared__ __align__(16) us16 dsm[];
    int t = threadIdx.x;
    int n0 = blockIdx.y * 128;
    int b = blockIdx.z;
    const us16* A  = g_wqk;
    const us16* Bp = g_x2b + (size_t)b * CHW;

    int warp = t >> 5, lane = t & 31;
    int wm = warp >> 2, wn = warp & 3;
    int r = lane >> 2, cp = (lane & 3) * 2;

    float acc[4][4][4];
#pragma unroll
    for (int i = 0; i < 4; i++)
#pragma unroll
        for (int j = 0; j < 4; j++)
#pragma unroll
            for (int q2 = 0; q2 < 4; q2++) acc[i][j][q2] = 0.f;

#pragma unroll
    for (int it = 0; it < 4; it++){
        int job = it*256 + t;
        int ar = job >> 3, asg = (job & 7) * 8;
        cpa16(&AS0(0,ar,asg), A + (size_t)ar*NC + asg);
        int bk = job >> 4, bn = (job & 15) * 8;
        cpa16(&BS0(0,bk,bn), Bp + (size_t)bk*NHW + n0 + bn);
    }
    asm volatile("cp.async.commit_group;\n");

    for (int kt = 0; kt < 8; kt++){
        int cur = kt & 1;
        asm volatile("cp.async.wait_group 0;\n");
        __syncthreads();
        if (kt < 7){
            int k0 = (kt+1) * 64;
            int nx = cur ^ 1;
#pragma unroll
            for (int it = 0; it < 4; it++){
                int job = it*256 + t;
                int ar = job >> 3, asg = (job & 7) * 8;
                cpa16(&AS0(nx,ar,asg), A + (size_t)ar*NC + k0 + asg);
                int bk = job >> 4, bn = (job & 15) * 8;
                cpa16(&BS0(nx,bk,bn), Bp + (size_t)(k0+bk)*NHW + n0 + bn);
            }
            asm volatile("cp.async.commit_group;\n");
        }
#pragma unroll
        for (int ks = 0; ks < 64; ks += 16){
            u32 af[4][4], bfr[4][2];
#pragma unroll
            for (int mi = 0; mi < 4; mi++){
                int rr = wm*64 + mi*16 + r;
                af[mi][0] = *(const u32*)&AS0(cur, rr,   ks+cp  );
                af[mi][1] = *(const u32*)&AS0(cur, rr+8, ks+cp  );
                af[mi][2] = *(const u32*)&AS0(cur, rr,   ks+cp+8);
                af[mi][3] = *(const u32*)&AS0(cur, rr+8, ks+cp+8);
            }
#pragma unroll
            for (int ni = 0; ni < 4; ni++){
                u32 sa = (u32)__cvta_generic_to_shared(&BS0(cur, ks + (lane & 15), wn*32 + ni*8));
                asm volatile("ldmatrix.sync.aligned.m8n8.x2.trans.shared.b16 {%0,%1}, [%2];"
                             : "=r"(bfr[ni][0]), "=r"(bfr[ni][1]) : "r"(sa));
            }
#pragma unroll
            for (int mi = 0; mi < 4; mi++)
#pragma unroll
                for (int ni = 0; ni < 4; ni++)
                    mma_bf16(acc[mi][ni], af[mi], bfr[ni]);
        }
    }
    __syncthreads();

#pragma unroll
    for (int mi = 0; mi < 4; mi++){
#pragma unroll
        for (int ni = 0; ni < 4; ni++){
            int pixl = wn*32 + ni*8 + cp;
#pragma unroll
            for (int rr2 = 0; rr2 < 2; rr2++){
                int ch = wm*64 + mi*16 + r + rr2*8;
                float bb = ch < 64 ? bias0[ch] : bias1[ch-64];
                STG0(pixl,   ch) = f2b(acc[mi][ni][rr2*2 + 0] + bb);
                STG0(pixl+1, ch) = f2b(acc[mi][ni][rr2*2 + 1] + bb);
            }
        }
    }
    __syncthreads();
    us16* dst = g_qkb + (size_t)b*NHW*128;
#pragma unroll
    for (int j = 0; j < 8; j++){
        int job = j*256 + t;
        int p = job >> 4, cseg = (job & 15) * 8;
        *(uint4*)(dst + (size_t)(n0+p)*128 + cseg) = *(uint4*)&STG0(p, cseg);
    }
}

// -------- energy dir0 (H direction): E_H, fixed w --------
__global__ __launch_bounds__(128) void k_energy0(){
    __shared__ __align__(16) us16 QK[64][136];
    int plane = blockIdx.x, b = blockIdx.y, t = threadIdx.x;
    const us16* src = g_qkb + (size_t)b*NHW*128;
#pragma unroll
    for (int j = 0; j < 8; j++){
        int job = j*128 + t;
        int row = job >> 4, cseg = (job & 15) * 8;
        size_t pix = (size_t)row*64 + plane;
        *(uint4*)&QK[row][cseg] = *(const uint4*)(src + pix*128 + cseg);
    }
    __syncthreads();

    int warp = t >> 5, lane = t & 31;
    int r = lane >> 2, cp = (lane & 3) * 2;
    float acc[8][4];
#pragma unroll
    for (int nt = 0; nt < 8; nt++)
#pragma unroll
        for (int q2 = 0; q2 < 4; q2++) acc[nt][q2] = 0.f;

#pragma unroll
    for (int ks = 0; ks < 64; ks += 16){
        u32 af[4];
        int rr = warp*16 + r;
        af[0] = *(const u32*)&QK[rr  ][ks+cp  ];
        af[1] = *(const u32*)&QK[rr+8][ks+cp  ];
        af[2] = *(const u32*)&QK[rr  ][ks+cp+8];
        af[3] = *(const u32*)&QK[rr+8][ks+cp+8];
#pragma unroll
        for (int nt = 0; nt < 8; nt++){
            u32 bf2[2];
            int nn = nt*8 + r;
            bf2[0] = *(const u32*)&QK[nn][64+ks+cp  ];
            bf2[1] = *(const u32*)&QK[nn][64+ks+cp+8];
            mma_bf16(acc[nt], af, bf2);
        }
    }

#pragma unroll
    for (int nt = 0; nt < 8; nt++){
        int n = nt*8 + cp;
#pragma unroll
        for (int rr2 = 0; rr2 < 2; rr2++){
            int m = warp*16 + r + rr2*8;
            size_t pix = (size_t)b*4096 + (size_t)m*64 + plane;
            *(float2*)&g_att[pix*128 + n] =
                make_float2(acc[nt][rr2*2 + 0], acc[nt][rr2*2 + 1]);
        }
    }
}

// -------- fused energy dir1 (W direction) + joint softmax over 128 --------
__global__ __launch_bounds__(128) void k_ensoft(){
    __shared__ __align__(16) us16 QK[64][136];
    __shared__ float EH[64][68];
    int plane = blockIdx.x, b = blockIdx.y, t = threadIdx.x;   // plane = h
    const us16* src = g_qkb + (size_t)b*NHW*128;
#pragma unroll
    for (int j = 0; j < 8; j++){
        int job = j*128 + t;
        int row = job >> 4, cseg = (job & 15) * 8;
        size_t pix = (size_t)plane*64 + row;
        *(uint4*)&QK[row][cseg] = *(const uint4*)(src + pix*128 + cseg);
    }
    const float* eh = g_att + ((size_t)b*4096 + (size_t)plane*64)*128;
#pragma unroll
    for (int j = 0; j < 8; j++){
        int job = j*128 + t;
        int row = job >> 4, c4 = (job & 15) * 4;
        *(float4*)&EH[row][c4] = *(const float4*)(eh + (size_t)row*128 + c4);
    }
    __syncthreads();

    int warp = t >> 5, lane = t & 31;
    int r = lane >> 2, cp = (lane & 3) * 2, cg = lane & 3;
    float acc[8][4];
#pragma unroll
    for (int nt = 0; nt < 8; nt++)
#pragma unroll
        for (int q2 = 0; q2 < 4; q2++) acc[nt][q2] = 0.f;

#pragma unroll
    for (int ks = 0; ks < 64; ks += 16){
        u32 af[4];
        int rr = warp*16 + r;
        af[0] = *(const u32*)&QK[rr  ][ks+cp  ];
        af[1] = *(const u32*)&QK[rr+8][ks+cp  ];
        af[2] = *(const u32*)&QK[rr  ][ks+cp+8];
        af[3] = *(const u32*)&QK[rr+8][ks+cp+8];
#pragma unroll
        for (int nt = 0; nt < 8; nt++){
            u32 bf2[2];
            int nn = nt*8 + r;
            bf2[0] = *(const u32*)&QK[nn][64+ks+cp  ];
            bf2[1] = *(const u32*)&QK[nn][64+ks+cp+8];
            mma_bf16(acc[nt], af, bf2);
        }
    }

#pragma unroll
    for (int rr2 = 0; rr2 < 2; rr2++){
        int m = warp*16 + r + rr2*8;
        float ew[16], ehv[16];
#pragma unroll
        for (int nt = 0; nt < 8; nt++){
            ew[nt*2]   = acc[nt][rr2*2];
            ew[nt*2+1] = acc[nt][rr2*2+1];
        }
        float mx = -1e30f;
#pragma unroll
        for (int u = 0; u < 16; u++){
            ehv[u] = EH[m][cg*16 + u];
            mx = fmaxf(mx, fmaxf(ew[u], ehv[u]));
        }
        mx = fmaxf(mx, __shfl_xor_sync(0xffffffffu, mx, 1));
        mx = fmaxf(mx, __shfl_xor_sync(0xffffffffu, mx, 2));
        float s = 0.f;
#pragma unroll
        for (int u = 0; u < 16; u++){
            ew[u]  = __expf(ew[u]  - mx);
            ehv[u] = __expf(ehv[u] - mx);
            s += ew[u] + ehv[u];
        }
        s += __shfl_xor_sync(0xffffffffu, s, 1);
        s += __shfl_xor_sync(0xffffffffu, s, 2);
        float inv = 1.f / s;
        us16* dst = g_attb + ((size_t)b*4096 + (size_t)plane*64 + m)*128;
#pragma unroll
        for (int u = 0; u < 16; u += 2)
            *(u32*)(dst + cg*16 + u) = pk2(ehv[u]*inv, ehv[u+1]*inv);
#pragma unroll
        for (int nt = 0; nt < 8; nt++)
            *(u32*)(dst + 64 + nt*8 + cp) = pk2(ew[nt*2]*inv, ew[nt*2+1]*inv);
    }
}

// -------- agg dir0 only (column attention) -> aggP channel-last --------
__global__ __launch_bounds__(256) void k_agg0(){
    __shared__ __align__(16) us16 Bs[64][72];
    __shared__ __align__(16) us16 As[2][128][72];
    int plane = blockIdx.x, b = blockIdx.y, t = threadIdx.x;   // plane = w
    const us16* X2 = g_xT2 + (size_t)b*CHW + plane*64;
    const us16* X1 = g_xT1 + (size_t)b*CHW + plane*64;
    const us16* attp = g_attb + ((size_t)b*4096 + plane)*128;
    const int istride = 8192;

    int warp = t >> 5, lane = t & 31;
    int r = lane >> 2, cp = (lane & 3) * 2;

#pragma unroll
    for (int it = 0; it < 4; it++){
        int job = it*256 + t;
        int rr = job >> 3, seg = (job & 7) * 8;
        cpa16(&As[0][rr][seg], X2 + (size_t)rr*4096 + seg);
    }
    asm volatile("cp.async.commit_group;\n");
#pragma unroll
    for (int it = 0; it < 2; it++){
        int job = it*256 + t;
        int i2 = job >> 3, seg = (job & 7) * 8;
        *(uint4*)&Bs[i2][seg] = *(const uint4*)(attp + (size_t)i2*istride + seg);
    }

    for (int i = 0; i < 8; i++){
        int cur = i & 1;
        if (i < 7){
            int c0n = ((i+1) >> 1) * 128, tseln = (i+1) & 1;
            const us16* Xp = (tseln ? X1 : X2) + (size_t)c0n * 4096;
            int nx = cur ^ 1;
#pragma unroll
            for (int it = 0; it < 4; it++){
                int job = it*256 + t;
                int rr = job >> 3, seg = (job & 7) * 8;
                cpa16(&As[nx][rr][seg], Xp + (size_t)rr*4096 + seg);
            }
            asm volatile("cp.async.commit_group;\n");
            asm volatile("cp.async.wait_group 1;\n");
        } else {
            asm volatile("cp.async.wait_group 0;\n");
        }
        __syncthreads();

        float acc[8][4];
#pragma unroll
        for (int nt = 0; nt < 8; nt++)
#pragma unroll
            for (int q2 = 0; q2 < 4; q2++) acc[nt][q2] = 0.f;
#pragma unroll
        for (int ks = 0; ks < 64; ks += 16){
            u32 af[4];
            int rr = warp*16 + r;
            af[0] = *(const u32*)&As[cur][rr  ][ks+cp  ];
            af[1] = *(const u32*)&As[cur][rr+8][ks+cp  ];
            af[2] = *(const u32*)&As[cur][rr  ][ks+cp+8];
            af[3] = *(const u32*)&As[cur][rr+8][ks+cp+8];
#pragma unroll
            for (int nt = 0; nt < 8; nt++){
                u32 bf2[2];
                int nn = nt*8 + r;
                bf2[0] = *(const u32*)&Bs[nn][ks+cp  ];
                bf2[1] = *(const u32*)&Bs[nn][ks+cp+8];
                mma_bf16(acc[nt], af, bf2);
            }
        }
        __syncthreads();

        us16* stg = &As[cur][0][0];
        int crow = warp*16 + r;
#pragma unroll
        for (int nt = 0; nt < 8; nt++){
            int n = nt*8 + cp;
            stg[n*136 + crow]         = f2b(acc[nt][0]);
            stg[(n+1)*136 + crow]     = f2b(acc[nt][1]);
            stg[n*136 + crow + 8]     = f2b(acc[nt][2]);
            stg[(n+1)*136 + crow + 8] = f2b(acc[nt][3]);
        }
        __syncthreads();

        int c0 = (i >> 1) * 128, tsel = i & 1;
        us16* dP = g_aggP + (size_t)tsel*BCHW + (size_t)b*CHW;
#pragma unroll
        for (int it = 0; it < 4; it++){
            int job = it*256 + t;
            int n = job >> 4, cseg = (job & 15) * 8;
            uint4 s = *(uint4*)&stg[n*136 + cseg];
            size_t pix = (size_t)n*64 + plane;
            *(uint4*)(dP + pix*512 + c0 + cseg) = s;
        }
        __syncthreads();
    }
}

// -------- fused agg dir1 + output GEMM --------
// block (hp, b, sel): rows 2hp, 2hp+1. Phase1: agg row attention into persistent
// smem B tile [128 pix][512 c] + merge aggP. Phase2: v_w GEMM over 4 m-tiles.
#define BG(i,j)     dsm2[(size_t)(i)*520 + (j)]
#define A2X(st,i,j) dsm2[66560 + (st)*9216 + (i)*72 + (j)]
#define ATT(ri,i,j) dsm2[84992 + (ri)*4608 + (i)*72 + (j)]
#define AGGEMM_SMEM (94208*2)
__global__ __launch_bounds__(256) void k_aggemm(
    const float* __restrict__ vb, const float* __restrict__ x2r,
    const float* __restrict__ x1r, const float* __restrict__ gam,
    float* __restrict__ out)
{
    extern __shared__ __align__(16) us16 dsm2[];
    int t = threadIdx.x;
    int hp = blockIdx.x, b = blockIdx.y, sel = blockIdx.z;
    const us16* X = (sel ? g_x1b : g_x2b) + (size_t)b*CHW;
    const us16* attb = g_attb + ((size_t)b*4096 + (size_t)2*hp*64)*128;

    int warp = t >> 5, lane = t & 31;
    int r = lane >> 2, cp = (lane & 3) * 2;

    // prologue: X chunk 0 (ri=0, cc=0) + both att tiles, one group
#pragma unroll
    for (int it = 0; it < 4; it++){
        int job = it*256 + t;
        int rr = job >> 3, seg = (job & 7) * 8;
        cpa16(&A2X(0,rr,seg), X + (size_t)rr*4096 + 2*hp*64 + seg);
        int ri = job >> 9, n = (job >> 3) & 63, sg2 = (job & 7) * 8;
        cpa16(&ATT(ri,n,sg2), attb + ((size_t)ri*64 + n)*128 + 64 + sg2);
    }
    asm volatile("cp.async.commit_group;\n");

    // ---------------- phase 1: aggregation into BG ----------------
    for (int i = 0; i < 8; i++){
        int cur = i & 1;
        int ri = i >> 2, cc = i & 3;
        if (i < 7){
            int rin = (i+1) >> 2, ccn = (i+1) & 3;
            int nx = cur ^ 1;
            const us16* Xp = X + (size_t)ccn*128*4096 + (2*hp + rin)*64;
#pragma unroll
            for (int it = 0; it < 4; it++){
                int job = it*256 + t;
                int rr = job >> 3, seg = (job & 7) * 8;
                cpa16(&A2X(nx,rr,seg), Xp + (size_t)rr*4096 + seg);
            }
            asm volatile("cp.async.commit_group;\n");
            asm volatile("cp.async.wait_group 1;\n");
        } else {
            asm volatile("cp.async.wait_group 0;\n");
        }
        __syncthreads();

        float acc[8][4];
#pragma unroll
        for (int nt = 0; nt < 8; nt++)
#pragma unroll
            for (int q2 = 0; q2 < 4; q2++) acc[nt][q2] = 0.f;
#pragma unroll
        for (int ks = 0; ks < 64; ks += 16){
            u32 af[4];
            int rr = warp*16 + r;
            af[0] = *(const u32*)&A2X(cur, rr,   ks+cp  );
            af[1] = *(const u32*)&A2X(cur, rr+8, ks+cp  );
            af[2] = *(const u32*)&A2X(cur, rr,   ks+cp+8);
            af[3] = *(const u32*)&A2X(cur, rr+8, ks+cp+8);
#pragma unroll
            for (int nt = 0; nt < 8; nt++){
                u32 bf2[2];
                int nn = nt*8 + r;
                bf2[0] = *(const u32*)&ATT(ri, nn, ks+cp  );
                bf2[1] = *(const u32*)&ATT(ri, nn, ks+cp+8);
                mma_bf16(acc[nt], af, bf2);
            }
        }

        // stage into persistent B tile (channel-last): BG[ri*64 + n][cc*128 + c]
        int crow = cc*128 + warp*16 + r;
#pragma unroll
        for (int nt = 0; nt < 8; nt++){
            int n = ri*64 + nt*8 + cp;
            BG(n,   crow  ) = f2b(acc[nt][0]);
            BG(n+1, crow  ) = f2b(acc[nt][1]);
            BG(n,   crow+8) = f2b(acc[nt][2]);
            BG(n+1, crow+8) = f2b(acc[nt][3]);
        }
        __syncthreads();
    }

    // merge dir0 partial from gmem into BG
    {
        const us16* dP = g_aggP + (size_t)sel*BCHW + (size_t)b*CHW + (size_t)hp*128*512;
#pragma unroll
        for (int it = 0; it < 32; it++){
            int job = it*256 + t;
            int pixL = job >> 6, cseg = (job & 63) * 8;
            uint4 p = *(const uint4*)(dP + (size_t)pixL*512 + cseg);
            uint4 s = *(uint4*)&BG(pixL, cseg);
            s.x = addbf2(s.x, p.x); s.y = addbf2(s.y, p.y);
            s.z = addbf2(s.z, p.z); s.w = addbf2(s.w, p.w);
            *(uint4*)&BG(pixL, cseg) = s;
        }
    }
    __syncthreads();

    // ---------------- phase 2: output GEMM (4 m-tiles x 8 k-chunks) ----------------
    int wm = warp >> 2, wn = warp & 3;
    float gval = gam[0];
    const float* xres = sel ? x1r : x2r;
    float* outp = out + (size_t)sel * BCHW;

    // prologue: chunk 0 (m0=0, kt=0) — A tile 128x64 = 1024 16B chunks = 4 iters
#pragma unroll
    for (int it = 0; it < 4; it++){
        int job = it*256 + t;
        int rr = job >> 3, seg = (job & 7) * 8;
        cpa16(&A2X(0,rr,seg), g_wv + (size_t)rr*NC + seg);
    }
    asm volatile("cp.async.commit_group;\n");

    float acc[4][4][4];
    for (int ch = 0; ch < 32; ch++){
        int cur = ch & 1;
        int kt = ch & 7;
        if (kt == 0){
#pragma unroll
            for (int i2 = 0; i2 < 4; i2++)
#pragma unroll
                for (int j2 = 0; j2 < 4; j2++)
#pragma unroll
                    for (int q2 = 0; q2 < 4; q2++) acc[i2][j2][q2] = 0.f;
        }
        if (ch < 31){
            int mN = (ch+1) >> 3, ktN = (ch+1) & 7;
            int nx = cur ^ 1;
            const us16* Ap = g_wv + (size_t)mN*128*NC + ktN*64;
#pragma unroll
            for (int it = 0; it < 4; it++){
                int job = it*256 + t;
                int rr = job >> 3, seg = (job & 7) * 8;
                cpa16(&A2X(nx,rr,seg), Ap + (size_t)rr*NC + seg);
            }
            asm volatile("cp.async.commit_group;\n");
            asm volatile("cp.async.wait_group 1;\n");
        } else {
            asm volatile("cp.async.wait_group 0;\n");
        }
        __syncthreads();

#pragma unroll
        for (int ks = 0; ks < 64; ks += 16){
            u32 af[4][4], bfr[4][2];
            int kabs = kt*64 + ks;
#pragma unroll
            for (int mi = 0; mi < 4; mi++){
                int rr = wm*64 + mi*16 + r;
                af[mi][0] = *(const u32*)&A2X(cur, rr,   ks+cp  );
                af[mi][1] = *(const u32*)&A2X(cur, rr+8, ks+cp  );
                af[mi][2] = *(const u32*)&A2X(cur, rr,   ks+cp+8);
                af[mi][3] = *(const u32*)&A2X(cur, rr+8, ks+cp+8);
            }
#pragma unroll
            for (int ni = 0; ni < 4; ni++){
                int nn = wn*32 + ni*8 + r;
                bfr[ni][0] = *(const u32*)&BG(nn, kabs+cp  );
                bfr[ni][1] = *(const u32*)&BG(nn, kabs+cp+8);
            }
#pragma unroll
            for (int mi = 0; mi < 4; mi++)
#pragma unroll
                for (int ni = 0; ni < 4; ni++)
                    mma_bf16(acc[mi][ni], af[mi], bfr[ni]);
        }

        if (kt == 7){
            int m0 = (ch >> 3) * 128;
#pragma unroll
            for (int mi = 0; mi < 4; mi++){
#pragma unroll
                for (int ni = 0; ni < 4; ni++){
                    int ng = hp*128 + wn*32 + ni*8 + cp;
#pragma unroll
                    for (int rr2 = 0; rr2 < 2; rr2++){
                        int oo = m0 + wm*64 + mi*16 + r + rr2*8;
                        float a0 = acc[mi][ni][rr2*2 + 0];
                        float a1 = acc[mi][ni][rr2*2 + 1];
                        float bb = vb[oo];
                        size_t oi = (size_t)(b*NC + oo)*NHW + ng;
                        float2 xr = *(const float2*)(xres + oi);
                        *(float2*)(outp + oi) = make_float2(gval*(a0+bb)+xr.x, gval*(a1+bb)+xr.y);
                    }
                }
            }
        }
        __syncthreads();
    }
}

// ------------------------- launch -------------------------
extern "C" void kernel_launch(void* const* d_in, const int* in_sizes, int n_in,
                              void* d_out, int out_size){
    const float* x2    = (const float*)d_in[0];
    const float* x1    = (const float*)d_in[1];
    const float* q_w   = (const float*)d_in[2];
    const float* q_b   = (const float*)d_in[3];
    const float* k_w   = (const float*)d_in[4];
    const float* k_b   = (const float*)d_in[5];
    const float* v_w   = (const float*)d_in[6];
    const float* v_b   = (const float*)d_in[7];
    const float* gamma = (const float*)d_in[8];
    float* out = (float*)d_out;

    cudaFuncSetAttribute(k_gemm0,  cudaFuncAttributeMaxDynamicSharedMemorySize, GEMM0_SMEM);
    cudaFuncSetAttribute(k_aggemm, cudaFuncAttributeMaxDynamicSharedMemorySize, AGGEMM_SMEM);

    k_prep<<<dim3(NB*NC, 3), 256>>>(x2, x1, q_w, k_w, v_w);
    k_gemm0<<<dim3(1, 32, NB), 256, GEMM0_SMEM>>>(q_b, k_b);
    k_energy0<<<dim3(64, NB), 128>>>();
    k_ensoft<<<dim3(64, NB), 128>>>();
    k_agg0<<<dim3(64, NB), 256>>>();
    k_aggemm<<<dim3(32, NB, 2), 256, AGGEMM_SMEM>>>(v_b, x2, x1, gamma, out);
}

// round 13
// speedup vs baseline: 1.2682x; 1.2682x over previous
#include <cuda_runtime.h>
#include <cuda_bf16.h>
#include <cuda_fp16.h>

typedef unsigned int u32;
typedef unsigned short us16;

#define NB 8
#define NC 512
#define NQ 64
#define NHW 4096
#define BCHW (NB*NC*NHW)
#define CHW  (NC*NHW)

// ------------------------- device scratch -------------------------
__device__ __align__(16) us16  g_x2b [BCHW];
__device__ __align__(16) us16  g_x1b [BCHW];
__device__ __align__(16) us16  g_xT2 [BCHW];
__device__ __align__(16) us16  g_xT1 [BCHW];
__device__ __align__(16) us16  g_qkb [NB*NHW*128];   // [b][pix][q0..63,k0..63] bf16
__device__ __align__(16) __half g_att[NB*NHW*64];    // E_H, fp16
__device__ __align__(16) us16  g_attb[NB*NHW*128];
__device__ __align__(16) us16  g_aggP[2*BCHW];       // dir0 partial, channel-last
__device__ __align__(16) us16  g_aggF[2*BCHW];       // final agg, channel-last
__device__ __align__(16) us16  g_wqk[128*NC];
__device__ __align__(16) us16  g_wv [NC*NC];

// ------------------------- helpers -------------------------
__device__ __forceinline__ us16 f2b(float f){
    __nv_bfloat16 h = __float2bfloat16(f);
    return *reinterpret_cast<us16*>(&h);
}
__device__ __forceinline__ float b2f(us16 u){
    __nv_bfloat16 h; *reinterpret_cast<us16*>(&h) = u;
    return __bfloat162float(h);
}
__device__ __forceinline__ u32 pk2(float a, float b){
    return (u32)f2b(a) | ((u32)f2b(b) << 16);
}
__device__ __forceinline__ u32 addbf2(u32 s, u32 p){
    float lo = b2f((us16)(s & 0xffff)) + b2f((us16)(p & 0xffff));
    float hi = b2f((us16)(s >> 16))    + b2f((us16)(p >> 16));
    return pk2(lo, hi);
}
__device__ __forceinline__ void mma_bf16(float* d, const u32* a, const u32* b){
    asm volatile(
        "mma.sync.aligned.m16n8k16.row.col.f32.bf16.bf16.f32 "
        "{%0,%1,%2,%3}, {%4,%5,%6,%7}, {%8,%9}, {%0,%1,%2,%3};\n"
        : "+f"(d[0]), "+f"(d[1]), "+f"(d[2]), "+f"(d[3])
        : "r"(a[0]), "r"(a[1]), "r"(a[2]), "r"(a[3]), "r"(b[0]), "r"(b[1]));
}
__device__ __forceinline__ void cpa16(void* s, const void* g){
    u32 sa = (u32)__cvta_generic_to_shared(s);
    asm volatile("cp.async.cg.shared.global [%0], [%1], 16;\n" :: "r"(sa), "l"(g));
}

// -------- prep: x -> bf16 (normal + transposed plane); y==2 converts weights --------
__global__ __launch_bounds__(256) void k_prep(const float* __restrict__ x2,
                                              const float* __restrict__ x1,
                                              const float* __restrict__ qw,
                                              const float* __restrict__ kw,
                                              const float* __restrict__ vw){
    int t = threadIdx.x;
    if (blockIdx.y == 2){
        if (blockIdx.x >= 1280) return;
        int i = blockIdx.x * 256 + t;
        if (i < 128 * NC){
            int o = i >> 9, c = i & 511;
            g_wqk[i] = f2b(o < 64 ? qw[o*NC + c] : kw[(o-64)*NC + c]);
        } else {
            int j = i - 128*NC;
            g_wv[j] = f2b(vw[j]);
        }
        return;
    }
    int plane = blockIdx.x, which = blockIdx.y;
    const float* x = (which ? x1    : x2   ) + (size_t)plane * 4096;
    us16*       on = (which ? g_x1b : g_x2b) + (size_t)plane * 4096;
    us16*       ot = (which ? g_xT1 : g_xT2) + (size_t)plane * 4096;
    __shared__ float sm[64][65];
    const float4* x4 = (const float4*)x;
#pragma unroll
    for (int j = 0; j < 4; j++){
        int idx4 = j*256 + t;
        float4 v = x4[idx4];
        int h = idx4 >> 4, w4 = (idx4 & 15) * 4;
        sm[h][w4  ] = v.x; sm[h][w4+1] = v.y;
        sm[h][w4+2] = v.z; sm[h][w4+3] = v.w;
        ((uint2*)on)[idx4] = make_uint2(pk2(v.x, v.y), pk2(v.z, v.w));
    }
    __syncthreads();
#pragma unroll
    for (int j = 0; j < 4; j++){
        int idx4 = j*256 + t;
        int w = idx4 >> 4, h4 = (idx4 & 15) * 4;
        ((uint2*)ot)[idx4] = make_uint2(pk2(sm[h4][w],   sm[h4+1][w]),
                                        pk2(sm[h4+2][w], sm[h4+3][w]));
    }
}

// -------- gemm0: [q_w;k_w](128x512) * x2b -> q,k channel-last bf16 (+bias) --------
#define AS0(st,i,j) dsm[(st)*9216 + (i)*72 + (j)]
#define BS0(st,i,j) dsm[18432 + (st)*8704 + (i)*136 + (j)]
#define STG0(p,c)   dsm[(p)*136 + (c)]
#define GEMM0_SMEM ((18432 + 2*8704) * 2)
__global__ __launch_bounds__(256) void k_gemm0(
    const float* __restrict__ bias0, const float* __restrict__ bias1)
{
    extern __shared__ __align__(16) us16 dsm[];
    int t = threadIdx.x;
    int n0 = blockIdx.y * 128;
    int b = blockIdx.z;
    const us16* A  = g_wqk;
    const us16* Bp = g_x2b + (size_t)b * CHW;

    int warp = t >> 5, lane = t & 31;
    int wm = warp >> 2, wn = warp & 3;
    int r = lane >> 2, cp = (lane & 3) * 2;

    float acc[4][4][4];
#pragma unroll
    for (int i = 0; i < 4; i++)
#pragma unroll
        for (int j = 0; j < 4; j++)
#pragma unroll
            for (int q2 = 0; q2 < 4; q2++) acc[i][j][q2] = 0.f;

#pragma unroll
    for (int it = 0; it < 4; it++){
        int job = it*256 + t;
        int ar = job >> 3, asg = (job & 7) * 8;
        cpa16(&AS0(0,ar,asg), A + (size_t)ar*NC + asg);
        int bk = job >> 4, bn = (job & 15) * 8;
        cpa16(&BS0(0,bk,bn), Bp + (size_t)bk*NHW + n0 + bn);
    }
    asm volatile("cp.async.commit_group;\n");

    for (int kt = 0; kt < 8; kt++){
        int cur = kt & 1;
        asm volatile("cp.async.wait_group 0;\n");
        __syncthreads();
        if (kt < 7){
            int k0 = (kt+1) * 64;
            int nx = cur ^ 1;
#pragma unroll
            for (int it = 0; it < 4; it++){
                int job = it*256 + t;
                int ar = job >> 3, asg = (job & 7) * 8;
                cpa16(&AS0(nx,ar,asg), A + (size_t)ar*NC + k0 + asg);
                int bk = job >> 4, bn = (job & 15) * 8;
                cpa16(&BS0(nx,bk,bn), Bp + (size_t)(k0+bk)*NHW + n0 + bn);
            }
            asm volatile("cp.async.commit_group;\n");
        }
#pragma unroll
        for (int ks = 0; ks < 64; ks += 16){
            u32 af[4][4], bfr[4][2];
#pragma unroll
            for (int mi = 0; mi < 4; mi++){
                int rr = wm*64 + mi*16 + r;
                af[mi][0] = *(const u32*)&AS0(cur, rr,   ks+cp  );
                af[mi][1] = *(const u32*)&AS0(cur, rr+8, ks+cp  );
                af[mi][2] = *(const u32*)&AS0(cur, rr,   ks+cp+8);
                af[mi][3] = *(const u32*)&AS0(cur, rr+8, ks+cp+8);
            }
#pragma unroll
            for (int ni = 0; ni < 4; ni++){
                u32 sa = (u32)__cvta_generic_to_shared(&BS0(cur, ks + (lane & 15), wn*32 + ni*8));
                asm volatile("ldmatrix.sync.aligned.m8n8.x2.trans.shared.b16 {%0,%1}, [%2];"
                             : "=r"(bfr[ni][0]), "=r"(bfr[ni][1]) : "r"(sa));
            }
#pragma unroll
            for (int mi = 0; mi < 4; mi++)
#pragma unroll
                for (int ni = 0; ni < 4; ni++)
                    mma_bf16(acc[mi][ni], af[mi], bfr[ni]);
        }
    }
    __syncthreads();

#pragma unroll
    for (int mi = 0; mi < 4; mi++){
#pragma unroll
        for (int ni = 0; ni < 4; ni++){
            int pixl = wn*32 + ni*8 + cp;
#pragma unroll
            for (int rr2 = 0; rr2 < 2; rr2++){
                int ch = wm*64 + mi*16 + r + rr2*8;
                float bb = ch < 64 ? bias0[ch] : bias1[ch-64];
                STG0(pixl,   ch) = f2b(acc[mi][ni][rr2*2 + 0] + bb);
                STG0(pixl+1, ch) = f2b(acc[mi][ni][rr2*2 + 1] + bb);
            }
        }
    }
    __syncthreads();
    us16* dst = g_qkb + (size_t)b*NHW*128;
#pragma unroll
    for (int j = 0; j < 8; j++){
        int job = j*256 + t;
        int p = job >> 4, cseg = (job & 15) * 8;
        *(uint4*)(dst + (size_t)(n0+p)*128 + cseg) = *(uint4*)&STG0(p, cseg);
    }
}

// -------- energy dir0 (H direction): E_H (fp16 out), fixed w --------
__global__ __launch_bounds__(128) void k_energy0(){
    __shared__ __align__(16) us16 QK[64][136];
    int plane = blockIdx.x, b = blockIdx.y, t = threadIdx.x;
    const us16* src = g_qkb + (size_t)b*NHW*128;
#pragma unroll
    for (int j = 0; j < 8; j++){
        int job = j*128 + t;
        int row = job >> 4, cseg = (job & 15) * 8;
        size_t pix = (size_t)row*64 + plane;
        *(uint4*)&QK[row][cseg] = *(const uint4*)(src + pix*128 + cseg);
    }
    __syncthreads();

    int warp = t >> 5, lane = t & 31;
    int r = lane >> 2, cp = (lane & 3) * 2;
    float acc[8][4];
#pragma unroll
    for (int nt = 0; nt < 8; nt++)
#pragma unroll
        for (int q2 = 0; q2 < 4; q2++) acc[nt][q2] = 0.f;

#pragma unroll
    for (int ks = 0; ks < 64; ks += 16){
        u32 af[4];
        int rr = warp*16 + r;
        af[0] = *(const u32*)&QK[rr  ][ks+cp  ];
        af[1] = *(const u32*)&QK[rr+8][ks+cp  ];
        af[2] = *(const u32*)&QK[rr  ][ks+cp+8];
        af[3] = *(const u32*)&QK[rr+8][ks+cp+8];
#pragma unroll
        for (int nt = 0; nt < 8; nt++){
            u32 bf2[2];
            int nn = nt*8 + r;
            bf2[0] = *(const u32*)&QK[nn][64+ks+cp  ];
            bf2[1] = *(const u32*)&QK[nn][64+ks+cp+8];
            mma_bf16(acc[nt], af, bf2);
        }
    }

#pragma unroll
    for (int nt = 0; nt < 8; nt++){
        int n = nt*8 + cp;
#pragma unroll
        for (int rr2 = 0; rr2 < 2; rr2++){
            int m = warp*16 + r + rr2*8;
            size_t pix = (size_t)b*4096 + (size_t)m*64 + plane;
            __half2 hv = __floats2half2_rn(acc[nt][rr2*2 + 0], acc[nt][rr2*2 + 1]);
            *(__half2*)&g_att[pix*64 + n] = hv;
        }
    }
}

// -------- fused energy dir1 (W direction) + joint softmax over 128 --------
__global__ __launch_bounds__(128) void k_ensoft(){
    __shared__ __align__(16) us16 QK[64][136];
    __shared__ float EH[64][68];
    int plane = blockIdx.x, b = blockIdx.y, t = threadIdx.x;   // plane = h
    const us16* src = g_qkb + (size_t)b*NHW*128;
#pragma unroll
    for (int j = 0; j < 8; j++){
        int job = j*128 + t;
        int row = job >> 4, cseg = (job & 15) * 8;
        size_t pix = (size_t)plane*64 + row;
        *(uint4*)&QK[row][cseg] = *(const uint4*)(src + pix*128 + cseg);
    }
    const __half* eh = g_att + ((size_t)b*4096 + (size_t)plane*64)*64;
#pragma unroll
    for (int j = 0; j < 4; j++){
        int job = j*128 + t;
        int row = job >> 3, seg = (job & 7) * 8;   // 8 halves per thread
        uint4 v = *(const uint4*)(eh + (size_t)row*64 + seg);
        const __half2* hp2 = (const __half2*)&v;
#pragma unroll
        for (int u = 0; u < 4; u++){
            float2 f = __half22float2(hp2[u]);
            EH[row][seg + u*2    ] = f.x;
            EH[row][seg + u*2 + 1] = f.y;
        }
    }
    __syncthreads();

    int warp = t >> 5, lane = t & 31;
    int r = lane >> 2, cp = (lane & 3) * 2, cg = lane & 3;
    float acc[8][4];
#pragma unroll
    for (int nt = 0; nt < 8; nt++)
#pragma unroll
        for (int q2 = 0; q2 < 4; q2++) acc[nt][q2] = 0.f;

#pragma unroll
    for (int ks = 0; ks < 64; ks += 16){
        u32 af[4];
        int rr = warp*16 + r;
        af[0] = *(const u32*)&QK[rr  ][ks+cp  ];
        af[1] = *(const u32*)&QK[rr+8][ks+cp  ];
        af[2] = *(const u32*)&QK[rr  ][ks+cp+8];
        af[3] = *(const u32*)&QK[rr+8][ks+cp+8];
#pragma unroll
        for (int nt = 0; nt < 8; nt++){
            u32 bf2[2];
            int nn = nt*8 + r;
            bf2[0] = *(const u32*)&QK[nn][64+ks+cp  ];
            bf2[1] = *(const u32*)&QK[nn][64+ks+cp+8];
            mma_bf16(acc[nt], af, bf2);
        }
    }

#pragma unroll
    for (int rr2 = 0; rr2 < 2; rr2++){
        int m = warp*16 + r + rr2*8;
        float ew[16], ehv[16];
#pragma unroll
        for (int nt = 0; nt < 8; nt++){
            ew[nt*2]   = acc[nt][rr2*2];
            ew[nt*2+1] = acc[nt][rr2*2+1];
        }
        float mx = -1e30f;
#pragma unroll
        for (int u = 0; u < 16; u++){
            ehv[u] = EH[m][cg*16 + u];
            mx = fmaxf(mx, fmaxf(ew[u], ehv[u]));
        }
        mx = fmaxf(mx, __shfl_xor_sync(0xffffffffu, mx, 1));
        mx = fmaxf(mx, __shfl_xor_sync(0xffffffffu, mx, 2));
        float s = 0.f;
#pragma unroll
        for (int u = 0; u < 16; u++){
            ew[u]  = __expf(ew[u]  - mx);
            ehv[u] = __expf(ehv[u] - mx);
            s += ew[u] + ehv[u];
        }
        s += __shfl_xor_sync(0xffffffffu, s, 1);
        s += __shfl_xor_sync(0xffffffffu, s, 2);
        float inv = 1.f / s;
        us16* dst = g_attb + ((size_t)b*4096 + (size_t)plane*64 + m)*128;
#pragma unroll
        for (int u = 0; u < 16; u += 2)
            *(u32*)(dst + cg*16 + u) = pk2(ehv[u]*inv, ehv[u+1]*inv);
#pragma unroll
        for (int nt = 0; nt < 8; nt++)
            *(u32*)(dst + 64 + nt*8 + cp) = pk2(ew[nt*2]*inv, ew[nt*2+1]*inv);
    }
}

// -------- aggregation (channel-last out), cp.async pipelined, dir1 fuses merge --------
__global__ __launch_bounds__(256) void k_agg(int dir){
    __shared__ __align__(16) us16 Bs[64][72];
    __shared__ __align__(16) us16 As[2][128][72];
    int plane = blockIdx.x, b = blockIdx.y, t = threadIdx.x;
    const us16* X2 = (dir ? g_x2b : g_xT2) + (size_t)b*CHW + plane*64;
    const us16* X1 = (dir ? g_x1b : g_xT1) + (size_t)b*CHW + plane*64;
    const us16* attp; int istride;
    if (dir == 0){ attp = g_attb + ((size_t)b*4096 + plane)*128;                 istride = 8192; }
    else         { attp = g_attb + ((size_t)b*4096 + (size_t)plane*64)*128 + 64; istride = 128;  }

    int warp = t >> 5, lane = t & 31;
    int r = lane >> 2, cp = (lane & 3) * 2;

#pragma unroll
    for (int it = 0; it < 4; it++){
        int job = it*256 + t;
        int rr = job >> 3, seg = (job & 7) * 8;
        cpa16(&As[0][rr][seg], X2 + (size_t)rr*4096 + seg);
    }
    asm volatile("cp.async.commit_group;\n");
#pragma unroll
    for (int it = 0; it < 2; it++){
        int job = it*256 + t;
        int i2 = job >> 3, seg = (job & 7) * 8;
        *(uint4*)&Bs[i2][seg] = *(const uint4*)(attp + (size_t)i2*istride + seg);
    }

    for (int i = 0; i < 8; i++){
        int cur = i & 1;
        if (i < 7){
            int c0n = ((i+1) >> 1) * 128, tseln = (i+1) & 1;
            const us16* Xp = (tseln ? X1 : X2) + (size_t)c0n * 4096;
            int nx = cur ^ 1;
#pragma unroll
            for (int it = 0; it < 4; it++){
                int job = it*256 + t;
                int rr = job >> 3, seg = (job & 7) * 8;
                cpa16(&As[nx][rr][seg], Xp + (size_t)rr*4096 + seg);
            }
            asm volatile("cp.async.commit_group;\n");
            asm volatile("cp.async.wait_group 1;\n");
        } else {
            asm volatile("cp.async.wait_group 0;\n");
        }
        __syncthreads();

        float acc[8][4];
#pragma unroll
        for (int nt = 0; nt < 8; nt++)
#pragma unroll
            for (int q2 = 0; q2 < 4; q2++) acc[nt][q2] = 0.f;
#pragma unroll
        for (int ks = 0; ks < 64; ks += 16){
            u32 af[4];
            int rr = warp*16 + r;
            af[0] = *(const u32*)&As[cur][rr  ][ks+cp  ];
            af[1] = *(const u32*)&As[cur][rr+8][ks+cp  ];
            af[2] = *(const u32*)&As[cur][rr  ][ks+cp+8];
            af[3] = *(const u32*)&As[cur][rr+8][ks+cp+8];
#pragma unroll
            for (int nt = 0; nt < 8; nt++){
                u32 bf2[2];
                int nn = nt*8 + r;
                bf2[0] = *(const u32*)&Bs[nn][ks+cp  ];
                bf2[1] = *(const u32*)&Bs[nn][ks+cp+8];
                mma_bf16(acc[nt], af, bf2);
            }
        }
        __syncthreads();

        us16* stg = &As[cur][0][0];
        int crow = warp*16 + r;
#pragma unroll
        for (int nt = 0; nt < 8; nt++){
            int n = nt*8 + cp;
            stg[n*136 + crow]         = f2b(acc[nt][0]);
            stg[(n+1)*136 + crow]     = f2b(acc[nt][1]);
            stg[n*136 + crow + 8]     = f2b(acc[nt][2]);
            stg[(n+1)*136 + crow + 8] = f2b(acc[nt][3]);
        }
        __syncthreads();

        int c0 = (i >> 1) * 128, tsel = i & 1;
        us16* dP = g_aggP + (size_t)tsel*BCHW + (size_t)b*CHW;
        us16* dF = g_aggF + (size_t)tsel*BCHW + (size_t)b*CHW;
#pragma unroll
        for (int it = 0; it < 4; it++){
            int job = it*256 + t;
            int n = job >> 4, cseg = (job & 15) * 8;
            uint4 s = *(uint4*)&stg[n*136 + cseg];
            size_t pix = dir ? ((size_t)plane*64 + n) : ((size_t)n*64 + plane);
            size_t off = pix*512 + c0 + cseg;
            if (dir == 0){
                *(uint4*)(dP + off) = s;
            } else {
                uint4 p = *(const uint4*)(dP + off);
                uint4 o4;
                o4.x = addbf2(s.x, p.x); o4.y = addbf2(s.y, p.y);
                o4.z = addbf2(s.z, p.z); o4.w = addbf2(s.w, p.w);
                *(uint4*)(dF + off) = o4;
            }
        }
        __syncthreads();
    }
}

// -------- output conv GEMM: v_w(512x512) * aggF(channel-last) + epilogue --------
#define AS1(st,i,j) dsm[(st)*9216 + (i)*72 + (j)]
#define BS1(st,i,j) dsm[18432 + (st)*9216 + (i)*72 + (j)]
#define GEMM1_SMEM (4*9216*2)
__global__ __launch_bounds__(256) void k_gemm1(
    const float* __restrict__ vb, const float* __restrict__ x2r,
    const float* __restrict__ x1r, const float* __restrict__ gam,
    float* __restrict__ out)
{
    extern __shared__ __align__(16) us16 dsm[];
    int t = threadIdx.x;
    int m0 = blockIdx.x * 128, n0 = blockIdx.y * 128;
    int b = blockIdx.z >> 1, sel = blockIdx.z & 1;
    const us16* A  = g_wv;
    const us16* Bp = g_aggF + (size_t)sel*BCHW + (size_t)b*CHW;

    int warp = t >> 5, lane = t & 31;
    int wm = warp >> 2, wn = warp & 3;
    int r = lane >> 2, cp = (lane & 3) * 2;

    float acc[4][4][4];
#pragma unroll
    for (int i = 0; i < 4; i++)
#pragma unroll
        for (int j = 0; j < 4; j++)
#pragma unroll
            for (int q2 = 0; q2 < 4; q2++) acc[i][j][q2] = 0.f;

#pragma unroll
    for (int it = 0; it < 4; it++){
        int job = it*256 + t;
        int rr = job >> 3, seg = (job & 7) * 8;
        cpa16(&AS1(0,rr,seg), A  + (size_t)(m0+rr)*NC  + seg);
        cpa16(&BS1(0,rr,seg), Bp + (size_t)(n0+rr)*512 + seg);
    }
    asm volatile("cp.async.commit_group;\n");

    for (int kt = 0; kt < 8; kt++){
        int cur = kt & 1;
        asm volatile("cp.async.wait_group 0;\n");
        __syncthreads();
        if (kt < 7){
            int k0 = (kt+1) * 64;
            int nx = cur ^ 1;
#pragma unroll
            for (int it = 0; it < 4; it++){
                int job = it*256 + t;
                int rr = job >> 3, seg = (job & 7) * 8;
                cpa16(&AS1(nx,rr,seg), A  + (size_t)(m0+rr)*NC  + k0 + seg);
                cpa16(&BS1(nx,rr,seg), Bp + (size_t)(n0+rr)*512 + k0 + seg);
            }
            asm volatile("cp.async.commit_group;\n");
        }
#pragma unroll
        for (int ks = 0; ks < 64; ks += 16){
            u32 af[4][4], bfr[4][2];
#pragma unroll
            for (int mi = 0; mi < 4; mi++){
                int rr = wm*64 + mi*16 + r;
                af[mi][0] = *(const u32*)&AS1(cur, rr,   ks+cp  );
                af[mi][1] = *(const u32*)&AS1(cur, rr+8, ks+cp  );
                af[mi][2] = *(const u32*)&AS1(cur, rr,   ks+cp+8);
                af[mi][3] = *(const u32*)&AS1(cur, rr+8, ks+cp+8);
            }
#pragma unroll
            for (int ni = 0; ni < 4; ni++){
                int nn = wn*32 + ni*8 + r;
                bfr[ni][0] = *(const u32*)&BS1(cur, nn, ks+cp  );
                bfr[ni][1] = *(const u32*)&BS1(cur, nn, ks+cp+8);
            }
#pragma unroll
            for (int mi = 0; mi < 4; mi++)
#pragma unroll
                for (int ni = 0; ni < 4; ni++)
                    mma_bf16(acc[mi][ni], af[mi], bfr[ni]);
        }
    }

    float gval = gam[0];
    const float* xres = sel ? x1r : x2r;
    float* outp = out + (size_t)sel * BCHW;
#pragma unroll
    for (int mi = 0; mi < 4; mi++){
#pragma unroll
        for (int ni = 0; ni < 4; ni++){
            int ng = n0 + wn*32 + ni*8 + cp;
#pragma unroll
            for (int rr2 = 0; rr2 < 2; rr2++){
                int oo = m0 + wm*64 + mi*16 + r + rr2*8;
                float a0 = acc[mi][ni][rr2*2 + 0];
                float a1 = acc[mi][ni][rr2*2 + 1];
                float bb = vb[oo];
                size_t oi = (size_t)(b*NC + oo)*NHW + ng;
                float2 xr = *(const float2*)(xres + oi);
                *(float2*)(outp + oi) = make_float2(gval*(a0+bb)+xr.x, gval*(a1+bb)+xr.y);
            }
        }
    }
}

// ------------------------- launch -------------------------
extern "C" void kernel_launch(void* const* d_in, const int* in_sizes, int n_in,
                              void* d_out, int out_size){
    const float* x2    = (const float*)d_in[0];
    const float* x1    = (const float*)d_in[1];
    const float* q_w   = (const float*)d_in[2];
    const float* q_b   = (const float*)d_in[3];
    const float* k_w   = (const float*)d_in[4];
    const float* k_b   = (const float*)d_in[5];
    const float* v_w   = (const float*)d_in[6];
    const float* v_b   = (const float*)d_in[7];
    const float* gamma = (const float*)d_in[8];
    float* out = (float*)d_out;

    cudaFuncSetAttribute(k_gemm0, cudaFuncAttributeMaxDynamicSharedMemorySize, GEMM0_SMEM);
    cudaFuncSetAttribute(k_gemm1, cudaFuncAttributeMaxDynamicSharedMemorySize, GEMM1_SMEM);

    k_prep<<<dim3(NB*NC, 3), 256>>>(x2, x1, q_w, k_w, v_w);
    k_gemm0<<<dim3(1, 32, NB), 256, GEMM0_SMEM>>>(q_b, k_b);
    k_energy0<<<dim3(64, NB), 128>>>();
    k_ensoft<<<dim3(64, NB), 128>>>();
    k_agg<<<dim3(64, NB), 256>>>(0);
    k_agg<<<dim3(64, NB), 256>>>(1);
    k_gemm1<<<dim3(4, 32, 16), 256, GEMM1_SMEM>>>(v_b, x2, x1, gamma, out);
}